// round 9
// baseline (speedup 1.0000x reference)
#include <cuda_runtime.h>
#include <math.h>
#include <stdint.h>

// Problem constants
#define NN    65536          // nodes
#define EE    1048576        // edges
#define BG    128            // graphs
#define NPG   512            // nodes per graph
#define KSEL  256            // top-k kept
#define NHID  128
#define PAD   64             // padded adjacency slots per node (deg mean 16, sigma 4)
#define CHUNK 32             // features per aggregation chunk

// ---------------- device scratch (no allocations allowed) ----------------
__device__ __align__(16) float g_tmp[NN * 128];     // GEMM output per layer
__device__ __align__(16) float g_H[NN * 384];       // concat(h1,h2,h3)
__device__ float g_dis[NN];
__device__ __align__(16) int g_cnt[NN];             // degree / scatter cursor
__device__ int   g_adj[NN * PAD];                   // padded adjacency (src ids)
__device__ float g_stmp[NN];
__device__ float g_score[NN];
__device__ __align__(16) float g_read[BG * 768];
__device__ __align__(16) float g_z1[BG * 256];
__device__ __align__(16) float g_z2[BG * 128];

// ---------------- adjacency build (no scan needed) ----------------
__global__ void k_zero_cnt() {
    int i = blockIdx.x * blockDim.x + threadIdx.x;   // 16384 threads, int4 each
    *reinterpret_cast<int4*>(g_cnt + i * 4) = make_int4(0, 0, 0, 0);
}

__global__ void k_scatter(const int* __restrict__ src, const int* __restrict__ dst) {
    int e = blockIdx.x * blockDim.x + threadIdx.x;
    if (e < EE) {
        int d = dst[e];
        int pos = atomicAdd(&g_cnt[d], 1);
        g_adj[(size_t)d * PAD + pos] = src[e];
    }
}

__global__ void k_dis() {
    int i = blockIdx.x * blockDim.x + threadIdx.x;
    if (i < NN) g_dis[i] = rsqrtf((float)g_cnt[i] + 1.0f);
}

// ---------------- tensor-core GEMM (3xTF32 mma.sync) ----------------
// C[N,128] = A[N,128(stride lda)] @ W[128,128].  One 128x128 tile per block,
// full K staged in padded smem (stride 132 kills the 8-way fragment-load
// conflict). 8 warps in 2x4 grid, 64x32 warp tile, m16n8k8 tf32 fragments.
// 3xTF32 split: D += Ahi*Bhi + Ahi*Blo + Alo*Bhi  (error ~2^-22, fp32-like).

__device__ __forceinline__ void split_tf32(float x, uint32_t& hi, uint32_t& lo) {
    uint32_t h;
    asm("cvt.rna.tf32.f32 %0, %1;" : "=r"(h) : "f"(x));
    float r = x - __uint_as_float(h);
    uint32_t l;
    asm("cvt.rna.tf32.f32 %0, %1;" : "=r"(l) : "f"(r));
    hi = h; lo = l;
}

__device__ __forceinline__ void mma8(float* c, const uint32_t* a, const uint32_t* b) {
    asm("mma.sync.aligned.m16n8k8.row.col.f32.tf32.tf32.f32 "
        "{%0,%1,%2,%3}, {%4,%5,%6,%7}, {%8,%9}, {%0,%1,%2,%3};"
        : "+f"(c[0]), "+f"(c[1]), "+f"(c[2]), "+f"(c[3])
        : "r"(a[0]), "r"(a[1]), "r"(a[2]), "r"(a[3]), "r"(b[0]), "r"(b[1]));
}

#define TCS 132   // padded smem row stride (floats); 132*4B = 528B = 33*16B (float4-aligned)

__global__ __launch_bounds__(256) void gemm_tc(const float* __restrict__ Aext,
                                               int useH, int colOff, int lda,
                                               const float* __restrict__ W) {
    extern __shared__ float smtc[];
    float* As = smtc;               // [128][TCS]  A tile, row-major [row][k]
    float* Bs = smtc + 128 * TCS;   // [128][TCS]  W as-is: [k][n]
    const float* A = useH ? (g_H + colOff) : Aext;
    const int tid = threadIdx.x;
    const int row0 = blockIdx.x * 128;

    // stage A tile + W (both 128x128) — 256 threads x 16 float4 each per matrix
    for (int q = tid; q < 128 * 32; q += 256) {
        int r = q >> 5, f = (q & 31) * 4;
        float4 v = *reinterpret_cast<const float4*>(A + (size_t)(row0 + r) * lda + f);
        *reinterpret_cast<float4*>(As + r * TCS + f) = v;
        float4 w = *reinterpret_cast<const float4*>(W + r * 128 + f);
        *reinterpret_cast<float4*>(Bs + r * TCS + f) = w;
    }
    __syncthreads();

    const int lane = tid & 31, wid = tid >> 5;
    const int gq = lane >> 2, t4 = lane & 3;   // groupID, thread-in-group
    const int wr = (wid >> 2) * 64;            // warp row offset (2 row-warps)
    const int wc = (wid & 3) * 32;             // warp col offset (4 col-warps)

    float c[4][4][4];
#pragma unroll
    for (int i = 0; i < 4; i++)
#pragma unroll
        for (int j = 0; j < 4; j++)
#pragma unroll
            for (int q = 0; q < 4; q++) c[i][j][q] = 0.f;

#pragma unroll 1
    for (int ks = 0; ks < 16; ks++) {
        const int kb = ks * 8;
        uint32_t ah[4][4], al[4][4], bh[4][2], bl[4][2];
        // A fragments (m16k8): a0 r=g,c=t4 ; a1 r=g+8 ; a2 c=t4+4 ; a3 both
#pragma unroll
        for (int i = 0; i < 4; i++) {
            int r0 = wr + i * 16 + gq;
            split_tf32(As[r0 * TCS + kb + t4],           ah[i][0], al[i][0]);
            split_tf32(As[(r0 + 8) * TCS + kb + t4],     ah[i][1], al[i][1]);
            split_tf32(As[r0 * TCS + kb + t4 + 4],       ah[i][2], al[i][2]);
            split_tf32(As[(r0 + 8) * TCS + kb + t4 + 4], ah[i][3], al[i][3]);
        }
        // B fragments (k8n8, col): b0 r(k)=t4,c(n)=g ; b1 r=t4+4
#pragma unroll
        for (int j = 0; j < 4; j++) {
            int nc = wc + j * 8 + gq;
            split_tf32(Bs[(kb + t4) * TCS + nc],     bh[j][0], bl[j][0]);
            split_tf32(Bs[(kb + t4 + 4) * TCS + nc], bh[j][1], bl[j][1]);
        }
#pragma unroll
        for (int i = 0; i < 4; i++)
#pragma unroll
            for (int j = 0; j < 4; j++) {
                mma8(c[i][j], ah[i], bh[j]);
                mma8(c[i][j], ah[i], bl[j]);
                mma8(c[i][j], al[i], bh[j]);
            }
    }

    // epilogue: c0,c1 at (r, 2t4 / 2t4+1); c2,c3 at (r+8, same cols)
#pragma unroll
    for (int i = 0; i < 4; i++)
#pragma unroll
        for (int j = 0; j < 4; j++) {
            int r = row0 + wr + i * 16 + gq;
            int col = wc + j * 8 + 2 * t4;
            *reinterpret_cast<float2*>(&g_tmp[(size_t)r * 128 + col]) =
                make_float2(c[i][j][0], c[i][j][1]);
            *reinterpret_cast<float2*>(&g_tmp[(size_t)(r + 8) * 128 + col]) =
                make_float2(c[i][j][2], c[i][j][3]);
        }
}

// ---------------- smem graph-tiled aggregation ----------------
// Block = (graph, 32-feature chunk). Stage the graph's 512x32 feature window
// (64KB) + per-node dis (2KB) in smem; all 16x neighbor reuse hits smem
// instead of L2. Warp per dst node, lane per feature; neighbor indices/weights
// broadcast via shfl. sfeat row stride = 32 floats (128B) => lane l always
// hits bank l: conflict-free.
__global__ __launch_bounds__(256) void k_agg_smem(const float* __restrict__ bias, int colOff) {
    extern __shared__ float sm[];
    float* sfeat = sm;                 // [NPG][CHUNK]
    float* sdis  = sm + NPG * CHUNK;   // [NPG]
    const int g = blockIdx.x >> 2;     // graph
    const int c = blockIdx.x & 3;      // feature chunk
    const int base = g * NPG;
    const int tid = threadIdx.x;

    for (int i = tid; i < NPG; i += 256) sdis[i] = g_dis[base + i];
    for (int q = tid; q < NPG * (CHUNK / 4); q += 256) {
        int n = q >> 3;
        int f = (q & 7) * 4;
        float4 v = *reinterpret_cast<const float4*>(
            g_tmp + (size_t)(base + n) * 128 + c * CHUNK + f);
        *reinterpret_cast<float4*>(sfeat + n * CHUNK + f) = v;
    }
    __syncthreads();

    const int warp = tid >> 5, lane = tid & 31;
    const float bv = bias[c * CHUNK + lane];
    for (int n = warp; n < NPG; n += 8) {
        const int node = base + n;
        const float di = sdis[n];
        float acc = sfeat[n * CHUNK + lane] * di * di;
        const int deg = g_cnt[node];
        for (int b = 0; b < deg; b += 32) {
            int myi = b + lane;
            int sidx = 0; float swt = 0.f;
            if (myi < deg) {
                sidx = g_adj[(size_t)node * PAD + myi] - base;
                swt  = sdis[sidx] * di;
            }
            int m = min(32, deg - b);
            for (int j = 0; j < m; j++) {
                int   sn = __shfl_sync(0xffffffffu, sidx, j);
                float w  = __shfl_sync(0xffffffffu, swt,  j);
                acc += sfeat[sn * CHUNK + lane] * w;
            }
        }
        g_H[(size_t)node * 384 + colOff + c * CHUNK + lane] = fmaxf(acc + bv, 0.f);
    }
}

// ---------------- score GEMV: warp per node, H[N,384] @ Ws[384] ----------------
__global__ __launch_bounds__(256) void k_sgemv(const float* __restrict__ Ws) {
    int gtid = blockIdx.x * blockDim.x + threadIdx.x;
    int node = gtid >> 5;
    int lane = gtid & 31;
    const float* h = g_H + (size_t)node * 384;
    float p = 0.f;
#pragma unroll
    for (int q = 0; q < 3; q++) {
        float4 hv = *reinterpret_cast<const float4*>(h + q * 128 + lane * 4);
        float4 wv = *reinterpret_cast<const float4*>(Ws + q * 128 + lane * 4);
        p += hv.x * wv.x + hv.y * wv.y + hv.z * wv.z + hv.w * wv.w;
    }
#pragma unroll
    for (int o = 16; o; o >>= 1) p += __shfl_down_sync(0xffffffff, p, o);
    if (lane == 0) g_stmp[node] = p;
}

__global__ void k_sagg(const float* __restrict__ bs) {
    int i = blockIdx.x * blockDim.x + threadIdx.x;
    if (i >= NN) return;
    float di = g_dis[i];
    float acc = g_stmp[i] * di * di;
    int deg = g_cnt[i];
    for (int p = 0; p < deg; p++) {
        int sn = g_adj[(size_t)i * PAD + p];
        acc += g_stmp[sn] * g_dis[sn] * di;
    }
    g_score[i] = acc + bs[0];
}

// ---------------- top-k + gate + max/mean readout: block per graph ----------------
__global__ __launch_bounds__(512) void k_pool() {
    __shared__ float sc[512];
    __shared__ float gate[512];
    __shared__ unsigned char sel[512];
    int g = blockIdx.x, t = threadIdx.x;
    float my = g_score[g * NPG + t];
    sc[t] = my;
    __syncthreads();
    int rank = 0;
#pragma unroll 8
    for (int j = 0; j < NPG; j++) {
        float o = sc[j];
        rank += (o > my) || (o == my && j < t);
    }
    sel[t]  = (rank < KSEL) ? 1 : 0;
    gate[t] = tanhf(my);
    __syncthreads();
    if (t < 384) {
        float mx = -3.4e38f, sm = 0.f;
        const float* base = g_H + (size_t)g * NPG * 384 + t;
        for (int n = 0; n < NPG; n++) {
            if (sel[n]) {
                float v = base[(size_t)n * 384] * gate[n];
                mx = fmaxf(mx, v);
                sm += v;
            }
        }
        g_read[g * 768 + t]       = mx;
        g_read[g * 768 + 384 + t] = sm * (1.0f / KSEL);
    }
}

// ---------------- MLP ----------------
__global__ __launch_bounds__(256) void k_mlp1(const float* __restrict__ W, const float* __restrict__ b) {
    __shared__ float r[768];
    int g = blockIdx.x, t = threadIdx.x;
    for (int k = t; k < 768; k += 256) r[k] = g_read[g * 768 + k];
    __syncthreads();
    float acc = b[t];
#pragma unroll 8
    for (int k = 0; k < 768; k++) acc += r[k] * W[(size_t)k * 256 + t];
    g_z1[g * 256 + t] = fmaxf(acc, 0.f);
}

__global__ __launch_bounds__(128) void k_mlp2(const float* __restrict__ W, const float* __restrict__ b) {
    __shared__ float r[256];
    int g = blockIdx.x, t = threadIdx.x;
    for (int k = t; k < 256; k += 128) r[k] = g_z1[g * 256 + k];
    __syncthreads();
    float acc = b[t];
#pragma unroll 8
    for (int k = 0; k < 256; k++) acc += r[k] * W[(size_t)k * 128 + t];
    g_z2[g * 128 + t] = fmaxf(acc, 0.f);
}

__global__ __launch_bounds__(32) void k_mlp3(const float* __restrict__ W, const float* __restrict__ b,
                                             float* __restrict__ out) {
    int g = blockIdx.x;
    int lane = threadIdx.x;
    __shared__ float logits[10];
    for (int c = 0; c < 10; c++) {
        float p = 0.f;
        for (int k = lane; k < 128; k += 32) p += g_z2[g * 128 + k] * W[k * 10 + c];
#pragma unroll
        for (int o = 16; o; o >>= 1) p += __shfl_down_sync(0xffffffff, p, o);
        if (lane == 0) logits[c] = p + b[c];
    }
    __syncwarp();
    if (lane == 0) {
        float m = logits[0];
        for (int c = 1; c < 10; c++) m = fmaxf(m, logits[c]);
        float s = 0.f;
        for (int c = 0; c < 10; c++) s += expf(logits[c] - m);
        float lse = logf(s);
        for (int c = 0; c < 10; c++) out[g * 10 + c] = logits[c] - m - lse;
    }
}

// ---------------- launch ----------------
extern "C" void kernel_launch(void* const* d_in, const int* in_sizes, int n_in,
                              void* d_out, int out_size) {
    const float* x   = (const float*)d_in[0];
    const int*   ei  = (const int*)  d_in[1];
    const float* W1  = (const float*)d_in[2];
    const float* b1  = (const float*)d_in[3];
    const float* W2  = (const float*)d_in[4];
    const float* b2  = (const float*)d_in[5];
    const float* W3  = (const float*)d_in[6];
    const float* b3  = (const float*)d_in[7];
    const float* Ws  = (const float*)d_in[8];
    const float* bs  = (const float*)d_in[9];
    const float* Wl1 = (const float*)d_in[10];
    const float* bl1 = (const float*)d_in[11];
    const float* Wl2 = (const float*)d_in[12];
    const float* bl2 = (const float*)d_in[13];
    const float* Wl3 = (const float*)d_in[14];
    const float* bl3 = (const float*)d_in[15];
    float* out = (float*)d_out;

    const int* src = ei;
    const int* dst = ei + EE;

    const int AGG_SMEM = NPG * CHUNK * 4 + NPG * 4;   // 67584 bytes
    const int TC_SMEM  = 2 * 128 * TCS * 4;           // 135168 bytes
    // Unconditional + idempotent (no static state; not stream ops; capture-safe).
    cudaFuncSetAttribute(k_agg_smem, cudaFuncAttributeMaxDynamicSharedMemorySize, AGG_SMEM);
    cudaFuncSetAttribute(gemm_tc,    cudaFuncAttributeMaxDynamicSharedMemorySize, TC_SMEM);

    // padded-adjacency build (no scan)
    k_zero_cnt<<<64, 256>>>();
    k_scatter<<<EE / 256, 256>>>(src, dst);
    k_dis<<<NN / 256, 256>>>();

    // GCN layer 1: x -> H[:,0:128]
    gemm_tc<<<NN / 128, 256, TC_SMEM>>>(x, 0, 0, 128, W1);
    k_agg_smem<<<BG * 4, 256, AGG_SMEM>>>(b1, 0);
    // GCN layer 2: H[:,0:128] -> H[:,128:256]
    gemm_tc<<<NN / 128, 256, TC_SMEM>>>(nullptr, 1, 0, 384, W2);
    k_agg_smem<<<BG * 4, 256, AGG_SMEM>>>(b2, 128);
    // GCN layer 3: H[:,128:256] -> H[:,256:384]
    gemm_tc<<<NN / 128, 256, TC_SMEM>>>(nullptr, 1, 128, 384, W3);
    k_agg_smem<<<BG * 4, 256, AGG_SMEM>>>(b3, 256);

    // score conv
    k_sgemv<<<(NN * 32) / 256, 256>>>(Ws);
    k_sagg<<<NN / 256, 256>>>(bs);

    // top-k + gated max/mean readout
    k_pool<<<BG, 512>>>();

    // MLP head
    k_mlp1<<<BG, 256>>>(Wl1, bl1);
    k_mlp2<<<BG, 128>>>(Wl2, bl2);
    k_mlp3<<<BG, 32>>>(Wl3, bl3, out);
}

// round 14
// speedup vs baseline: 1.7773x; 1.7773x over previous
#include <cuda_runtime.h>
#include <math.h>
#include <stdint.h>

// Problem constants
#define NN    65536          // nodes
#define EE    1048576        // edges
#define BG    128            // graphs
#define NPG   512            // nodes per graph
#define KSEL  256            // top-k kept
#define NHID  128
#define PAD   64             // padded adjacency slots per node (deg mean 16, sigma 4)

// ---------------- device scratch (no allocations allowed) ----------------
__device__ __align__(16) float g_tmp[NN * 128];     // GEMM output per layer
__device__ __align__(16) float g_H[NN * 384];       // concat(h1,h2,h3)
__device__ float g_dis[NN];
__device__ __align__(16) int g_cnt[NN];             // degree / scatter cursor
__device__ int   g_adj[NN * PAD];                   // padded adjacency (src ids)
__device__ float g_stmp[NN];
__device__ float g_score[NN];
__device__ __align__(16) float g_read[BG * 768];
__device__ __align__(16) float g_z1[BG * 256];
__device__ __align__(16) float g_z2[BG * 128];

// ---------------- adjacency build (no scan needed) ----------------
__global__ void k_zero_cnt() {
    int i = blockIdx.x * blockDim.x + threadIdx.x;   // 16384 threads, int4 each
    *reinterpret_cast<int4*>(g_cnt + i * 4) = make_int4(0, 0, 0, 0);
}

__global__ void k_scatter(const int* __restrict__ src, const int* __restrict__ dst) {
    int e = blockIdx.x * blockDim.x + threadIdx.x;
    if (e < EE) {
        int d = dst[e];
        int pos = atomicAdd(&g_cnt[d], 1);
        g_adj[(size_t)d * PAD + pos] = src[e];
    }
}

__global__ void k_dis() {
    int i = blockIdx.x * blockDim.x + threadIdx.x;
    if (i < NN) g_dis[i] = rsqrtf((float)g_cnt[i] + 1.0f);
}

// ---------------- tensor-core GEMM (3xTF32 mma.sync) ----------------
// C[N,128] = A[N,128(stride lda)] @ W[128,128].  One 128x128 tile per block.
// K staged in 64-wide halves to cut smem 135KB -> 68KB => 2 CTAs/SM (was 1).
// 8 warps in 2x4 grid, 64x32 warp tile, m16n8k8 tf32 fragments.
// 3xTF32 split: D += Ahi*Bhi + Ahi*Blo + Alo*Bhi  (error ~2^-22, fp32-like;
// validated rel_err 4.3e-8 in R9).

__device__ __forceinline__ void split_tf32(float x, uint32_t& hi, uint32_t& lo) {
    uint32_t h;
    asm("cvt.rna.tf32.f32 %0, %1;" : "=r"(h) : "f"(x));
    float r = x - __uint_as_float(h);
    uint32_t l;
    asm("cvt.rna.tf32.f32 %0, %1;" : "=r"(l) : "f"(r));
    hi = h; lo = l;
}

__device__ __forceinline__ void mma8(float* c, const uint32_t* a, const uint32_t* b) {
    asm("mma.sync.aligned.m16n8k8.row.col.f32.tf32.tf32.f32 "
        "{%0,%1,%2,%3}, {%4,%5,%6,%7}, {%8,%9}, {%0,%1,%2,%3};"
        : "+f"(c[0]), "+f"(c[1]), "+f"(c[2]), "+f"(c[3])
        : "r"(a[0]), "r"(a[1]), "r"(a[2]), "r"(a[3]), "r"(b[0]), "r"(b[1]));
}

#define TCSA 68    // A smem row stride (floats): 68 mod 32 = 4 -> frag loads conflict-free
#define TCSB 136   // B smem row stride: 136 mod 32 = 8 -> frag loads conflict-free
#define TC_SMEM_BYTES (128 * TCSA * 4 + 64 * TCSB * 4)   // 34816 + 34816 = 69632

__global__ __launch_bounds__(256, 2) void gemm_tc(const float* __restrict__ Aext,
                                                  int useH, int colOff, int lda,
                                                  const float* __restrict__ W) {
    extern __shared__ float smtc[];
    float* As = smtc;                // [128][TCSA]  A rows x 64 k-cols of current half
    float* Bs = smtc + 128 * TCSA;   // [64][TCSB]   k-rows x 128 n-cols of current half
    const float* A = useH ? (g_H + colOff) : Aext;
    const int tid = threadIdx.x;
    const int row0 = blockIdx.x * 128;

    const int lane = tid & 31, wid = tid >> 5;
    const int gq = lane >> 2, t4 = lane & 3;   // groupID, thread-in-group
    const int wr = (wid >> 2) * 64;            // warp row offset (2 row-warps)
    const int wc = (wid & 3) * 32;             // warp col offset (4 col-warps)

    float c[4][4][4];
#pragma unroll
    for (int i = 0; i < 4; i++)
#pragma unroll
        for (int j = 0; j < 4; j++)
#pragma unroll
            for (int q = 0; q < 4; q++) c[i][j][q] = 0.f;

#pragma unroll 1
    for (int h = 0; h < 2; h++) {
        // stage A half: 128 rows x 64 cols = 2048 float4 (8 per thread)
        for (int q = tid; q < 128 * 16; q += 256) {
            int r = q >> 4, f = (q & 15) * 4;
            float4 v = *reinterpret_cast<const float4*>(
                A + (size_t)(row0 + r) * lda + h * 64 + f);
            *reinterpret_cast<float4*>(As + r * TCSA + f) = v;
        }
        // stage W half: k-rows h*64..h*64+63, all 128 n-cols = 2048 float4
        for (int q = tid; q < 64 * 32; q += 256) {
            int r = q >> 5, f = (q & 31) * 4;
            float4 w = *reinterpret_cast<const float4*>(W + (size_t)(h * 64 + r) * 128 + f);
            *reinterpret_cast<float4*>(Bs + r * TCSB + f) = w;
        }
        __syncthreads();

#pragma unroll 1
        for (int ks = 0; ks < 8; ks++) {
            const int kb = ks * 8;
            uint32_t ah[4][4], al[4][4], bh[4][2], bl[4][2];
            // A fragments (m16k8): a0 r=g,c=t4 ; a1 r=g+8 ; a2 c=t4+4 ; a3 both
#pragma unroll
            for (int i = 0; i < 4; i++) {
                int r0 = wr + i * 16 + gq;
                split_tf32(As[r0 * TCSA + kb + t4],            ah[i][0], al[i][0]);
                split_tf32(As[(r0 + 8) * TCSA + kb + t4],      ah[i][1], al[i][1]);
                split_tf32(As[r0 * TCSA + kb + t4 + 4],        ah[i][2], al[i][2]);
                split_tf32(As[(r0 + 8) * TCSA + kb + t4 + 4],  ah[i][3], al[i][3]);
            }
            // B fragments (k8n8, col): b0 r(k)=t4,c(n)=g ; b1 r=t4+4
#pragma unroll
            for (int j = 0; j < 4; j++) {
                int nc = wc + j * 8 + gq;
                split_tf32(Bs[(kb + t4) * TCSB + nc],     bh[j][0], bl[j][0]);
                split_tf32(Bs[(kb + t4 + 4) * TCSB + nc], bh[j][1], bl[j][1]);
            }
#pragma unroll
            for (int i = 0; i < 4; i++)
#pragma unroll
                for (int j = 0; j < 4; j++) {
                    mma8(c[i][j], ah[i], bh[j]);
                    mma8(c[i][j], ah[i], bl[j]);
                    mma8(c[i][j], al[i], bh[j]);
                }
        }
        __syncthreads();
    }

    // epilogue: c0,c1 at (r, 2t4 / 2t4+1); c2,c3 at (r+8, same cols)
#pragma unroll
    for (int i = 0; i < 4; i++)
#pragma unroll
        for (int j = 0; j < 4; j++) {
            int r = row0 + wr + i * 16 + gq;
            int col = wc + j * 8 + 2 * t4;
            *reinterpret_cast<float2*>(&g_tmp[(size_t)r * 128 + col]) =
                make_float2(c[i][j][0], c[i][j][1]);
            *reinterpret_cast<float2*>(&g_tmp[(size_t)(r + 8) * 128 + col]) =
                make_float2(c[i][j][2], c[i][j][3]);
        }
}

// ---------------- GCN aggregation: warp per node, float4 per lane ----------------
// R3-proven design (no SHFL on the edge critical path). 256 threads = 8 warps
// = 8 nodes/block; lane covers 4 features (coalesced 512B row reads, L2-served).
// Next edge index/weight prefetched past current row FMAs.
__global__ __launch_bounds__(256) void k_agg(const float* __restrict__ bias, int colOff) {
    int warp = (blockIdx.x * blockDim.x + threadIdx.x) >> 5;
    int lane = threadIdx.x & 31;
    if (warp >= NN) return;
    const int i = warp;
    float di = g_dis[i];
    float4 acc = *reinterpret_cast<const float4*>(g_tmp + (size_t)i * 128 + lane * 4);
    float self = di * di;
    acc.x *= self; acc.y *= self; acc.z *= self; acc.w *= self;
    const int* adj = g_adj + (size_t)i * PAD;
    int n = g_cnt[i];
    if (n > 0) {
        int sn = adj[0];
        float w = g_dis[sn] * di;
        for (int p = 1; p < n; p++) {
            int sn_next = adj[p];                 // prefetch next index
            float w_next = g_dis[sn_next] * di;   // and its weight
            float4 v = *reinterpret_cast<const float4*>(g_tmp + (size_t)sn * 128 + lane * 4);
            acc.x += v.x * w; acc.y += v.y * w;
            acc.z += v.z * w; acc.w += v.w * w;
            sn = sn_next; w = w_next;
        }
        float4 v = *reinterpret_cast<const float4*>(g_tmp + (size_t)sn * 128 + lane * 4);
        acc.x += v.x * w; acc.y += v.y * w;
        acc.z += v.z * w; acc.w += v.w * w;
    }
    float4 bv = *reinterpret_cast<const float4*>(bias + lane * 4);
    acc.x = fmaxf(acc.x + bv.x, 0.f);
    acc.y = fmaxf(acc.y + bv.y, 0.f);
    acc.z = fmaxf(acc.z + bv.z, 0.f);
    acc.w = fmaxf(acc.w + bv.w, 0.f);
    *reinterpret_cast<float4*>(g_H + (size_t)i * 384 + colOff + lane * 4) = acc;
}

// ---------------- score GEMV: warp per node, H[N,384] @ Ws[384] ----------------
__global__ __launch_bounds__(256) void k_sgemv(const float* __restrict__ Ws) {
    int gtid = blockIdx.x * blockDim.x + threadIdx.x;
    int node = gtid >> 5;
    int lane = gtid & 31;
    const float* h = g_H + (size_t)node * 384;
    float p = 0.f;
#pragma unroll
    for (int q = 0; q < 3; q++) {
        float4 hv = *reinterpret_cast<const float4*>(h + q * 128 + lane * 4);
        float4 wv = *reinterpret_cast<const float4*>(Ws + q * 128 + lane * 4);
        p += hv.x * wv.x + hv.y * wv.y + hv.z * wv.z + hv.w * wv.w;
    }
#pragma unroll
    for (int o = 16; o; o >>= 1) p += __shfl_down_sync(0xffffffff, p, o);
    if (lane == 0) g_stmp[node] = p;
}

__global__ void k_sagg(const float* __restrict__ bs) {
    int i = blockIdx.x * blockDim.x + threadIdx.x;
    if (i >= NN) return;
    float di = g_dis[i];
    float acc = g_stmp[i] * di * di;
    int deg = g_cnt[i];
    const int* adj = g_adj + (size_t)i * PAD;
    for (int p = 0; p < deg; p++) {
        int sn = adj[p];
        acc += g_stmp[sn] * g_dis[sn] * di;
    }
    g_score[i] = acc + bs[0];
}

// ---------------- top-k + gate + max/mean readout: block per graph ----------------
__global__ __launch_bounds__(512) void k_pool() {
    __shared__ float sc[512];
    __shared__ float gate[512];
    __shared__ unsigned char sel[512];
    int g = blockIdx.x, t = threadIdx.x;
    float my = g_score[g * NPG + t];
    sc[t] = my;
    __syncthreads();
    int rank = 0;
#pragma unroll 8
    for (int j = 0; j < NPG; j++) {
        float o = sc[j];
        rank += (o > my) || (o == my && j < t);
    }
    sel[t]  = (rank < KSEL) ? 1 : 0;
    gate[t] = tanhf(my);
    __syncthreads();
    if (t < 384) {
        float mx = -3.4e38f, sm = 0.f;
        const float* base = g_H + (size_t)g * NPG * 384 + t;
        for (int n = 0; n < NPG; n++) {
            if (sel[n]) {
                float v = base[(size_t)n * 384] * gate[n];
                mx = fmaxf(mx, v);
                sm += v;
            }
        }
        g_read[g * 768 + t]       = mx;
        g_read[g * 768 + 384 + t] = sm * (1.0f / KSEL);
    }
}

// ---------------- MLP ----------------
__global__ __launch_bounds__(256) void k_mlp1(const float* __restrict__ W, const float* __restrict__ b) {
    __shared__ float r[768];
    int g = blockIdx.x, t = threadIdx.x;
    for (int k = t; k < 768; k += 256) r[k] = g_read[g * 768 + k];
    __syncthreads();
    float acc = b[t];
#pragma unroll 8
    for (int k = 0; k < 768; k++) acc += r[k] * W[(size_t)k * 256 + t];
    g_z1[g * 256 + t] = fmaxf(acc, 0.f);
}

__global__ __launch_bounds__(128) void k_mlp2(const float* __restrict__ W, const float* __restrict__ b) {
    __shared__ float r[256];
    int g = blockIdx.x, t = threadIdx.x;
    for (int k = t; k < 256; k += 128) r[k] = g_z1[g * 256 + k];
    __syncthreads();
    float acc = b[t];
#pragma unroll 8
    for (int k = 0; k < 256; k++) acc += r[k] * W[(size_t)k * 128 + t];
    g_z2[g * 128 + t] = fmaxf(acc, 0.f);
}

__global__ __launch_bounds__(32) void k_mlp3(const float* __restrict__ W, const float* __restrict__ b,
                                             float* __restrict__ out) {
    int g = blockIdx.x;
    int lane = threadIdx.x;
    __shared__ float logits[10];
    for (int c = 0; c < 10; c++) {
        float p = 0.f;
        for (int k = lane; k < 128; k += 32) p += g_z2[g * 128 + k] * W[k * 10 + c];
#pragma unroll
        for (int o = 16; o; o >>= 1) p += __shfl_down_sync(0xffffffff, p, o);
        if (lane == 0) logits[c] = p + b[c];
    }
    __syncwarp();
    if (lane == 0) {
        float m = logits[0];
        for (int c = 1; c < 10; c++) m = fmaxf(m, logits[c]);
        float s = 0.f;
        for (int c = 0; c < 10; c++) s += expf(logits[c] - m);
        float lse = logf(s);
        for (int c = 0; c < 10; c++) out[g * 10 + c] = logits[c] - m - lse;
    }
}

// ---------------- launch ----------------
extern "C" void kernel_launch(void* const* d_in, const int* in_sizes, int n_in,
                              void* d_out, int out_size) {
    const float* x   = (const float*)d_in[0];
    const int*   ei  = (const int*)  d_in[1];
    const float* W1  = (const float*)d_in[2];
    const float* b1  = (const float*)d_in[3];
    const float* W2  = (const float*)d_in[4];
    const float* b2  = (const float*)d_in[5];
    const float* W3  = (const float*)d_in[6];
    const float* b3  = (const float*)d_in[7];
    const float* Ws  = (const float*)d_in[8];
    const float* bs  = (const float*)d_in[9];
    const float* Wl1 = (const float*)d_in[10];
    const float* bl1 = (const float*)d_in[11];
    const float* Wl2 = (const float*)d_in[12];
    const float* bl2 = (const float*)d_in[13];
    const float* Wl3 = (const float*)d_in[14];
    const float* bl3 = (const float*)d_in[15];
    float* out = (float*)d_out;

    const int* src = ei;
    const int* dst = ei + EE;

    // Unconditional + idempotent (no static state; not a stream op; capture-safe).
    cudaFuncSetAttribute(gemm_tc, cudaFuncAttributeMaxDynamicSharedMemorySize, TC_SMEM_BYTES);

    // padded-adjacency build (no scan)
    k_zero_cnt<<<64, 256>>>();
    k_scatter<<<EE / 256, 256>>>(src, dst);
    k_dis<<<NN / 256, 256>>>();

    // GCN layer 1: x -> H[:,0:128]
    gemm_tc<<<NN / 128, 256, TC_SMEM_BYTES>>>(x, 0, 0, 128, W1);
    k_agg<<<NN / 8, 256>>>(b1, 0);
    // GCN layer 2: H[:,0:128] -> H[:,128:256]
    gemm_tc<<<NN / 128, 256, TC_SMEM_BYTES>>>(nullptr, 1, 0, 384, W2);
    k_agg<<<NN / 8, 256>>>(b2, 128);
    // GCN layer 3: H[:,128:256] -> H[:,256:384]
    gemm_tc<<<NN / 128, 256, TC_SMEM_BYTES>>>(nullptr, 1, 128, 384, W3);
    k_agg<<<NN / 8, 256>>>(b3, 256);

    // score conv
    k_sgemv<<<(NN * 32) / 256, 256>>>(Ws);
    k_sagg<<<NN / 256, 256>>>(bs);

    // top-k + gated max/mean readout
    k_pool<<<BG, 512>>>();

    // MLP head
    k_mlp1<<<BG, 256>>>(Wl1, bl1);
    k_mlp2<<<BG, 128>>>(Wl2, bl2);
    k_mlp3<<<BG, 32>>>(Wl3, bl3, out);
}